// round 2
// baseline (speedup 1.0000x reference)
#include <cuda_runtime.h>
#include <cstdint>

#define IN_DIM  1024
#define HID_DIM 4096
#define OUT_DIM 1024
#define N_EXP   8
#define BATCH   8192

// ---------------- scratch (device globals; no allocation) ----------------
__device__ int   g_counts[N_EXP];
__device__ int   g_cursor[N_EXP];
__device__ int   g_offsets[N_EXP];
__device__ int   g_expert_of[BATCH];
__device__ int   g_perm[BATCH];                       // gathered row -> original token
__device__ float g_xg[(size_t)BATCH * IN_DIM];        // gathered x (tf32-rounded)
__device__ float g_hg[(size_t)BATCH * HID_DIM];       // gathered hidden (tf32-rounded)

__device__ __forceinline__ float tf32r(float f) {
    float o;
    asm("cvt.rna.tf32.f32 %0, %1;" : "=f"(o) : "f"(f));
    return o;
}

// ---------------- small kernels ----------------
__global__ void zero_kernel() {
    int t = threadIdx.x;
    if (t < N_EXP) { g_counts[t] = 0; g_cursor[t] = 0; }
}

__global__ void router_kernel(const float* __restrict__ x,
                              const float* __restrict__ rw,
                              const float* __restrict__ rb,
                              float* __restrict__ route_out) {
    int warp = (blockIdx.x * blockDim.x + threadIdx.x) >> 5;
    int lane = threadIdx.x & 31;
    if (warp >= BATCH) return;
    const float* xr = x + (size_t)warp * IN_DIM;
    float acc[N_EXP];
#pragma unroll
    for (int e = 0; e < N_EXP; e++) acc[e] = 0.f;
    for (int k = lane; k < IN_DIM; k += 32) {
        float xv = xr[k];
        const float4* w4 = reinterpret_cast<const float4*>(rw + (size_t)k * N_EXP);
        float4 w0 = w4[0], w1 = w4[1];
        acc[0] += xv * w0.x; acc[1] += xv * w0.y;
        acc[2] += xv * w0.z; acc[3] += xv * w0.w;
        acc[4] += xv * w1.x; acc[5] += xv * w1.y;
        acc[6] += xv * w1.z; acc[7] += xv * w1.w;
    }
#pragma unroll
    for (int e = 0; e < N_EXP; e++) {
#pragma unroll
        for (int off = 16; off > 0; off >>= 1)
            acc[e] += __shfl_down_sync(0xffffffffu, acc[e], off);
    }
    if (lane == 0) {
        float best = acc[0] + rb[0]; int bi = 0;
#pragma unroll
        for (int e = 1; e < N_EXP; e++) {
            float v = acc[e] + rb[e];
            if (v > best) { best = v; bi = e; }   // first-max wins == jnp.argmax
        }
        g_expert_of[warp] = bi;
        atomicAdd(&g_counts[bi], 1);
        float* ro = route_out + (size_t)warp * N_EXP;
#pragma unroll
        for (int e = 0; e < N_EXP; e++) ro[e] = (e == bi) ? 1.f : 0.f;
    }
}

__global__ void scan_kernel() {
    if (threadIdx.x == 0) {
        int s = 0;
        for (int e = 0; e < N_EXP; e++) { g_offsets[e] = s; s += g_counts[e]; }
    }
}

__global__ void gather_kernel(const float* __restrict__ x) {
    int warp = (blockIdx.x * blockDim.x + threadIdx.x) >> 5;
    int lane = threadIdx.x & 31;
    if (warp >= BATCH) return;
    int e = g_expert_of[warp];
    int pos = 0;
    if (lane == 0) {
        pos = g_offsets[e] + atomicAdd(&g_cursor[e], 1);
        g_perm[pos] = warp;
    }
    pos = __shfl_sync(0xffffffffu, pos, 0);
    const float4* src = reinterpret_cast<const float4*>(x + (size_t)warp * IN_DIM);
    float4* dst = reinterpret_cast<float4*>(g_xg + (size_t)pos * IN_DIM);
    for (int i = lane; i < IN_DIM / 4; i += 32) {
        float4 v = src[i];
        v.x = tf32r(v.x); v.y = tf32r(v.y); v.z = tf32r(v.z); v.w = tf32r(v.w);
        dst[i] = v;
    }
}

// ---------------- tf32 mma.sync GEMM ----------------
constexpr int BM = 128, BN = 128, BK = 32, THREADS = 256;
constexpr int AST = BK + 4;   // 36 floats: conflict-free A frag reads
constexpr int BST = BN + 4;   // 132 floats: conflict-free B frag reads
constexpr int SMEM_BYTES = (2 * BM * AST + 2 * BK * BST) * 4;  // 70656 B

__device__ __forceinline__ void cp_async16(float* sm, const float* g, bool p) {
    uint32_t s = (uint32_t)__cvta_generic_to_shared(sm);
    int bytes = p ? 16 : 0;
    asm volatile("cp.async.cg.shared.global [%0], [%1], 16, %2;\n"
                 :: "r"(s), "l"(g), "r"(bytes));
}
__device__ __forceinline__ void cp_commit() { asm volatile("cp.async.commit_group;\n"); }
template <int N> __device__ __forceinline__ void cp_wait() {
    asm volatile("cp.async.wait_group %0;\n" :: "n"(N));
}

__device__ __forceinline__ void mma_tf32(float* c, const uint32_t* a, const uint32_t* b) {
    asm volatile(
        "mma.sync.aligned.m16n8k8.row.col.f32.tf32.tf32.f32 "
        "{%0,%1,%2,%3}, {%4,%5,%6,%7}, {%8,%9}, {%0,%1,%2,%3};\n"
        : "+f"(c[0]), "+f"(c[1]), "+f"(c[2]), "+f"(c[3])
        : "r"(a[0]), "r"(a[1]), "r"(a[2]), "r"(a[3]), "r"(b[0]), "r"(b[1]));
}

template <bool EXPERT>
__global__ __launch_bounds__(THREADS)
void gemm_tf32_kernel(const float* __restrict__ Bglob,
                      const float* __restrict__ biasGlob,
                      float* __restrict__ outGlob) {
    constexpr int Ksz = EXPERT ? IN_DIM : HID_DIM;
    constexpr int Nsz = EXPERT ? HID_DIM : OUT_DIM;
    constexpr int KT = Ksz / BK;

    int M;
    const float *A, *B, *bias;
    float* C;
    if constexpr (EXPERT) {
        int e = blockIdx.z;
        M    = g_counts[e];
        A    = g_xg + (size_t)g_offsets[e] * IN_DIM;
        B    = Bglob + (size_t)e * IN_DIM * HID_DIM;
        bias = biasGlob + (size_t)e * HID_DIM;
        C    = g_hg + (size_t)g_offsets[e] * HID_DIM;
    } else {
        M = BATCH; A = g_hg; B = Bglob; bias = biasGlob; C = outGlob;
    }
    int m_blk = blockIdx.y * BM;
    if (m_blk >= M) return;     // ragged per-expert M: cheap early-exit
    int n_blk = blockIdx.x * BN;

    extern __shared__ float smem[];
    float* As = smem;                    // [2][BM][AST], row-major (m,k)
    float* Bs = smem + 2 * BM * AST;     // [2][BK][BST], row-major (k,n)

    int tid = threadIdx.x;
    int a_row = tid >> 3;
    int a_col = (tid & 7) * 4;
    int b_row = tid >> 5;
    int b_col = (tid & 31) * 4;

    auto load_tiles = [&](int kt, int s) {
        float* Ad = As + s * BM * AST;
#pragma unroll
        for (int i = 0; i < 4; i++) {
            int r = a_row + i * 32;
            int gr = m_blk + r;
            bool ok = gr < M;
            const float* src = A + (size_t)(ok ? gr : 0) * Ksz + kt * BK + a_col;
            cp_async16(Ad + r * AST + a_col, src, ok);
        }
        float* Bd = Bs + s * BK * BST;
#pragma unroll
        for (int i = 0; i < 4; i++) {
            int r = b_row + i * 8;
            const float* src = B + (size_t)(kt * BK + r) * Nsz + n_blk + b_col;
            cp_async16(Bd + r * BST + b_col, src, true);
        }
        cp_commit();
    };

    float acc[4][4][4];
#pragma unroll
    for (int i = 0; i < 4; i++)
#pragma unroll
        for (int j = 0; j < 4; j++)
#pragma unroll
            for (int q = 0; q < 4; q++) acc[i][j][q] = 0.f;

    int lane = tid & 31, warp = tid >> 5;
    int wm = warp & 1, wn = warp >> 1;     // 2 warps along M, 4 along N
    int gq = lane >> 2, tg = lane & 3;

    load_tiles(0, 0);
    int cur = 0;
    for (int kt = 0; kt < KT; kt++) {
        if (kt + 1 < KT) { load_tiles(kt + 1, cur ^ 1); cp_wait<1>(); }
        else             { cp_wait<0>(); }
        __syncthreads();
        float* Ab = As + cur * BM * AST;
        float* Bb = Bs + cur * BK * BST;
#pragma unroll
        for (int ks = 0; ks < 4; ks++) {
            int k0 = ks * 8 + tg;
            uint32_t af[4][4], bf[4][2];
#pragma unroll
            for (int i = 0; i < 4; i++) {
                int r = wm * 64 + i * 16 + gq;
                af[i][0] = __float_as_uint(Ab[r * AST + k0]);
                af[i][1] = __float_as_uint(Ab[(r + 8) * AST + k0]);
                af[i][2] = __float_as_uint(Ab[r * AST + k0 + 4]);
                af[i][3] = __float_as_uint(Ab[(r + 8) * AST + k0 + 4]);
            }
#pragma unroll
            for (int j = 0; j < 4; j++) {
                int n = wn * 32 + j * 8 + gq;
                bf[j][0] = __float_as_uint(tf32r(Bb[k0 * BST + n]));
                bf[j][1] = __float_as_uint(tf32r(Bb[(k0 + 4) * BST + n]));
            }
#pragma unroll
            for (int i = 0; i < 4; i++)
#pragma unroll
                for (int j = 0; j < 4; j++)
                    mma_tf32(acc[i][j], af[i], bf[j]);
        }
        __syncthreads();
        cur ^= 1;
    }

    // epilogue
#pragma unroll
    for (int i = 0; i < 4; i++) {
        int r0 = m_blk + wm * 64 + i * 16 + gq;
        int r1 = r0 + 8;
#pragma unroll
        for (int j = 0; j < 4; j++) {
            int c = n_blk + wn * 32 + j * 8 + tg * 2;
            float bv0 = bias[c], bv1 = bias[c + 1];
            float v00 = acc[i][j][0] + bv0;
            float v01 = acc[i][j][1] + bv1;
            float v10 = acc[i][j][2] + bv0;
            float v11 = acc[i][j][3] + bv1;
            if constexpr (EXPERT) {
                if (r0 < M) {
                    C[(size_t)r0 * Nsz + c]     = tf32r(v00);
                    C[(size_t)r0 * Nsz + c + 1] = tf32r(v01);
                }
                if (r1 < M) {
                    C[(size_t)r1 * Nsz + c]     = tf32r(v10);
                    C[(size_t)r1 * Nsz + c + 1] = tf32r(v11);
                }
            } else {
                int o0 = g_perm[r0], o1 = g_perm[r1];   // scatter rows back
                C[(size_t)o0 * Nsz + c]     = v00;
                C[(size_t)o0 * Nsz + c + 1] = v01;
                C[(size_t)o1 * Nsz + c]     = v10;
                C[(size_t)o1 * Nsz + c + 1] = v11;
            }
        }
    }
}

// ---------------- launch ----------------
extern "C" void kernel_launch(void* const* d_in, const int* in_sizes, int n_in,
                              void* d_out, int out_size) {
    const float* x        = (const float*)d_in[0];
    const float* router_w = (const float*)d_in[1];
    const float* router_b = (const float*)d_in[2];
    const float* expert_w = (const float*)d_in[3];
    const float* expert_b = (const float*)d_in[4];
    const float* proj_w   = (const float*)d_in[5];
    const float* proj_b   = (const float*)d_in[6];

    float* out       = (float*)d_out;
    float* route_out = out + (size_t)BATCH * OUT_DIM;   // [out | one_hot]

    cudaFuncSetAttribute(gemm_tf32_kernel<true>,
                         cudaFuncAttributeMaxDynamicSharedMemorySize, SMEM_BYTES);
    cudaFuncSetAttribute(gemm_tf32_kernel<false>,
                         cudaFuncAttributeMaxDynamicSharedMemorySize, SMEM_BYTES);

    zero_kernel<<<1, 32>>>();
    router_kernel<<<BATCH / 8, 256>>>(x, router_w, router_b, route_out);
    scan_kernel<<<1, 1>>>();
    gather_kernel<<<BATCH / 8, 256>>>(x);
    gemm_tf32_kernel<true><<<dim3(HID_DIM / BN, BATCH / BM, N_EXP),
                             THREADS, SMEM_BYTES>>>(expert_w, expert_b, nullptr);
    gemm_tf32_kernel<false><<<dim3(OUT_DIM / BN, BATCH / BM, 1),
                              THREADS, SMEM_BYTES>>>(proj_w, proj_b, out);
}

// round 3
// speedup vs baseline: 1.0005x; 1.0005x over previous
#include <cuda_runtime.h>
#include <cstdint>

#define IN_DIM  1024
#define HID_DIM 4096
#define OUT_DIM 1024
#define N_EXP   8
#define BATCH   8192

// ---------------- scratch (device globals; no allocation) ----------------
__device__ int   g_counts[N_EXP];
__device__ int   g_cursor[N_EXP];
__device__ int   g_offsets[N_EXP];
__device__ int   g_expert_of[BATCH];
__device__ int   g_perm[BATCH];                       // gathered row -> original token
__device__ float g_xg[(size_t)BATCH * IN_DIM];        // gathered x (tf32-rounded)
__device__ float g_hg[(size_t)BATCH * HID_DIM];       // gathered hidden (tf32-rounded)

__device__ __forceinline__ float tf32r(float f) {
    float o;
    asm("cvt.rna.tf32.f32 %0, %1;" : "=f"(o) : "f"(f));
    return o;
}

// ---------------- small kernels ----------------
__global__ void zero_kernel() {
    int t = threadIdx.x;
    if (t < N_EXP) { g_counts[t] = 0; g_cursor[t] = 0; }
}

__global__ void router_kernel(const float* __restrict__ x,
                              const float* __restrict__ rw,
                              const float* __restrict__ rb,
                              float* __restrict__ route_out) {
    int warp = (blockIdx.x * blockDim.x + threadIdx.x) >> 5;
    int lane = threadIdx.x & 31;
    if (warp >= BATCH) return;
    const float* xr = x + (size_t)warp * IN_DIM;
    float acc[N_EXP];
#pragma unroll
    for (int e = 0; e < N_EXP; e++) acc[e] = 0.f;
    for (int k = lane; k < IN_DIM; k += 32) {
        float xv = xr[k];
        const float4* w4 = reinterpret_cast<const float4*>(rw + (size_t)k * N_EXP);
        float4 w0 = w4[0], w1 = w4[1];
        acc[0] += xv * w0.x; acc[1] += xv * w0.y;
        acc[2] += xv * w0.z; acc[3] += xv * w0.w;
        acc[4] += xv * w1.x; acc[5] += xv * w1.y;
        acc[6] += xv * w1.z; acc[7] += xv * w1.w;
    }
#pragma unroll
    for (int e = 0; e < N_EXP; e++) {
#pragma unroll
        for (int off = 16; off > 0; off >>= 1)
            acc[e] += __shfl_down_sync(0xffffffffu, acc[e], off);
    }
    if (lane == 0) {
        float best = acc[0] + rb[0]; int bi = 0;
#pragma unroll
        for (int e = 1; e < N_EXP; e++) {
            float v = acc[e] + rb[e];
            if (v > best) { best = v; bi = e; }   // first-max wins == jnp.argmax
        }
        g_expert_of[warp] = bi;
        atomicAdd(&g_counts[bi], 1);
        float* ro = route_out + (size_t)warp * N_EXP;
#pragma unroll
        for (int e = 0; e < N_EXP; e++) ro[e] = (e == bi) ? 1.f : 0.f;
    }
}

__global__ void scan_kernel() {
    if (threadIdx.x == 0) {
        int s = 0;
        for (int e = 0; e < N_EXP; e++) { g_offsets[e] = s; s += g_counts[e]; }
    }
}

__global__ void gather_kernel(const float* __restrict__ x) {
    int warp = (blockIdx.x * blockDim.x + threadIdx.x) >> 5;
    int lane = threadIdx.x & 31;
    if (warp >= BATCH) return;
    int e = g_expert_of[warp];
    int pos = 0;
    if (lane == 0) {
        pos = g_offsets[e] + atomicAdd(&g_cursor[e], 1);
        g_perm[pos] = warp;
    }
    pos = __shfl_sync(0xffffffffu, pos, 0);
    const float4* src = reinterpret_cast<const float4*>(x + (size_t)warp * IN_DIM);
    float4* dst = reinterpret_cast<float4*>(g_xg + (size_t)pos * IN_DIM);
    for (int i = lane; i < IN_DIM / 4; i += 32) {
        float4 v = src[i];
        v.x = tf32r(v.x); v.y = tf32r(v.y); v.z = tf32r(v.z); v.w = tf32r(v.w);
        dst[i] = v;
    }
}

// ---------------- tf32 mma.sync GEMM ----------------
constexpr int BM = 128, BN = 128, BK = 32, THREADS = 256;
constexpr int AST = BK + 4;   // 36 floats: conflict-free A frag reads
constexpr int BST = BN + 4;   // 132 floats: conflict-free B frag reads
constexpr int SMEM_BYTES = (2 * BM * AST + 2 * BK * BST) * 4;  // 70656 B

__device__ __forceinline__ void cp_async16(float* sm, const float* g, bool p) {
    uint32_t s = (uint32_t)__cvta_generic_to_shared(sm);
    int bytes = p ? 16 : 0;
    asm volatile("cp.async.cg.shared.global [%0], [%1], 16, %2;\n"
                 :: "r"(s), "l"(g), "r"(bytes));
}
__device__ __forceinline__ void cp_commit() { asm volatile("cp.async.commit_group;\n"); }
template <int N> __device__ __forceinline__ void cp_wait() {
    asm volatile("cp.async.wait_group %0;\n" :: "n"(N));
}

__device__ __forceinline__ void mma_tf32(float* c, const uint32_t* a, const uint32_t* b) {
    asm volatile(
        "mma.sync.aligned.m16n8k8.row.col.f32.tf32.tf32.f32 "
        "{%0,%1,%2,%3}, {%4,%5,%6,%7}, {%8,%9}, {%0,%1,%2,%3};\n"
        : "+f"(c[0]), "+f"(c[1]), "+f"(c[2]), "+f"(c[3])
        : "r"(a[0]), "r"(a[1]), "r"(a[2]), "r"(a[3]), "r"(b[0]), "r"(b[1]));
}

template <bool EXPERT>
__global__ __launch_bounds__(THREADS)
void gemm_tf32_kernel(const float* __restrict__ Bglob,
                      const float* __restrict__ biasGlob,
                      float* __restrict__ outGlob) {
    constexpr int Ksz = EXPERT ? IN_DIM : HID_DIM;
    constexpr int Nsz = EXPERT ? HID_DIM : OUT_DIM;
    constexpr int KT = Ksz / BK;

    int M;
    const float *A, *B, *bias;
    float* C;
    if constexpr (EXPERT) {
        int e = blockIdx.z;
        M    = g_counts[e];
        A    = g_xg + (size_t)g_offsets[e] * IN_DIM;
        B    = Bglob + (size_t)e * IN_DIM * HID_DIM;
        bias = biasGlob + (size_t)e * HID_DIM;
        C    = g_hg + (size_t)g_offsets[e] * HID_DIM;
    } else {
        M = BATCH; A = g_hg; B = Bglob; bias = biasGlob; C = outGlob;
    }
    int m_blk = blockIdx.y * BM;
    if (m_blk >= M) return;     // ragged per-expert M: cheap early-exit
    int n_blk = blockIdx.x * BN;

    extern __shared__ float smem[];
    float* As = smem;                    // [2][BM][AST], row-major (m,k)
    float* Bs = smem + 2 * BM * AST;     // [2][BK][BST], row-major (k,n)

    int tid = threadIdx.x;
    int a_row = tid >> 3;
    int a_col = (tid & 7) * 4;
    int b_row = tid >> 5;
    int b_col = (tid & 31) * 4;

    auto load_tiles = [&](int kt, int s) {
        float* Ad = As + s * BM * AST;
#pragma unroll
        for (int i = 0; i < 4; i++) {
            int r = a_row + i * 32;
            int gr = m_blk + r;
            bool ok = gr < M;
            const float* src = A + (size_t)(ok ? gr : 0) * Ksz + kt * BK + a_col;
            cp_async16(Ad + r * AST + a_col, src, ok);
        }
        float* Bd = Bs + s * BK * BST;
#pragma unroll
        for (int i = 0; i < 4; i++) {
            int r = b_row + i * 8;
            const float* src = B + (size_t)(kt * BK + r) * Nsz + n_blk + b_col;
            cp_async16(Bd + r * BST + b_col, src, true);
        }
        cp_commit();
    };

    float acc[4][4][4];
#pragma unroll
    for (int i = 0; i < 4; i++)
#pragma unroll
        for (int j = 0; j < 4; j++)
#pragma unroll
            for (int q = 0; q < 4; q++) acc[i][j][q] = 0.f;

    int lane = tid & 31, warp = tid >> 5;
    int wm = warp & 1, wn = warp >> 1;     // 2 warps along M, 4 along N
    int gq = lane >> 2, tg = lane & 3;

    load_tiles(0, 0);
    int cur = 0;
    for (int kt = 0; kt < KT; kt++) {
        if (kt + 1 < KT) { load_tiles(kt + 1, cur ^ 1); cp_wait<1>(); }
        else             { cp_wait<0>(); }
        __syncthreads();
        float* Ab = As + cur * BM * AST;
        float* Bb = Bs + cur * BK * BST;
#pragma unroll
        for (int ks = 0; ks < 4; ks++) {
            int k0 = ks * 8 + tg;
            uint32_t af[4][4], bf[4][2];
#pragma unroll
            for (int i = 0; i < 4; i++) {
                int r = wm * 64 + i * 16 + gq;
                af[i][0] = __float_as_uint(Ab[r * AST + k0]);
                af[i][1] = __float_as_uint(Ab[(r + 8) * AST + k0]);
                af[i][2] = __float_as_uint(Ab[r * AST + k0 + 4]);
                af[i][3] = __float_as_uint(Ab[(r + 8) * AST + k0 + 4]);
            }
#pragma unroll
            for (int j = 0; j < 4; j++) {
                int n = wn * 32 + j * 8 + gq;
                bf[j][0] = __float_as_uint(tf32r(Bb[k0 * BST + n]));
                bf[j][1] = __float_as_uint(tf32r(Bb[(k0 + 4) * BST + n]));
            }
#pragma unroll
            for (int i = 0; i < 4; i++)
#pragma unroll
                for (int j = 0; j < 4; j++)
                    mma_tf32(acc[i][j], af[i], bf[j]);
        }
        __syncthreads();
        cur ^= 1;
    }

    // epilogue
#pragma unroll
    for (int i = 0; i < 4; i++) {
        int r0 = m_blk + wm * 64 + i * 16 + gq;
        int r1 = r0 + 8;
#pragma unroll
        for (int j = 0; j < 4; j++) {
            int c = n_blk + wn * 32 + j * 8 + tg * 2;
            float bv0 = bias[c], bv1 = bias[c + 1];
            float v00 = acc[i][j][0] + bv0;
            float v01 = acc[i][j][1] + bv1;
            float v10 = acc[i][j][2] + bv0;
            float v11 = acc[i][j][3] + bv1;
            if constexpr (EXPERT) {
                if (r0 < M) {
                    C[(size_t)r0 * Nsz + c]     = tf32r(v00);
                    C[(size_t)r0 * Nsz + c + 1] = tf32r(v01);
                }
                if (r1 < M) {
                    C[(size_t)r1 * Nsz + c]     = tf32r(v10);
                    C[(size_t)r1 * Nsz + c + 1] = tf32r(v11);
                }
            } else {
                int o0 = g_perm[r0], o1 = g_perm[r1];   // scatter rows back
                C[(size_t)o0 * Nsz + c]     = v00;
                C[(size_t)o0 * Nsz + c + 1] = v01;
                C[(size_t)o1 * Nsz + c]     = v10;
                C[(size_t)o1 * Nsz + c + 1] = v11;
            }
        }
    }
}

// ---------------- launch ----------------
extern "C" void kernel_launch(void* const* d_in, const int* in_sizes, int n_in,
                              void* d_out, int out_size) {
    const float* x        = (const float*)d_in[0];
    const float* router_w = (const float*)d_in[1];
    const float* router_b = (const float*)d_in[2];
    const float* expert_w = (const float*)d_in[3];
    const float* expert_b = (const float*)d_in[4];
    const float* proj_w   = (const float*)d_in[5];
    const float* proj_b   = (const float*)d_in[6];

    float* out       = (float*)d_out;
    float* route_out = out + (size_t)BATCH * OUT_DIM;   // [out | one_hot]

    cudaFuncSetAttribute(gemm_tf32_kernel<true>,
                         cudaFuncAttributeMaxDynamicSharedMemorySize, SMEM_BYTES);
    cudaFuncSetAttribute(gemm_tf32_kernel<false>,
                         cudaFuncAttributeMaxDynamicSharedMemorySize, SMEM_BYTES);

    zero_kernel<<<1, 32>>>();
    router_kernel<<<BATCH / 8, 256>>>(x, router_w, router_b, route_out);
    scan_kernel<<<1, 1>>>();
    gather_kernel<<<BATCH / 8, 256>>>(x);
    gemm_tf32_kernel<true><<<dim3(HID_DIM / BN, BATCH / BM, N_EXP),
                             THREADS, SMEM_BYTES>>>(expert_w, expert_b, nullptr);
    gemm_tf32_kernel<false><<<dim3(OUT_DIM / BN, BATCH / BM, 1),
                              THREADS, SMEM_BYTES>>>(proj_w, proj_b, out);
}

// round 4
// speedup vs baseline: 1.0045x; 1.0040x over previous
#include <cuda_runtime.h>
#include <cstdint>

#define IN_DIM  1024
#define HID_DIM 4096
#define OUT_DIM 1024
#define N_EXP   8
#define BATCH   8192

// ---------------- scratch (device globals; no allocation) ----------------
__device__ int   g_counts[N_EXP];
__device__ int   g_cursor[N_EXP];
__device__ int   g_offsets[N_EXP];
__device__ int   g_expert_of[BATCH];
__device__ int   g_perm[BATCH];                       // gathered row -> original token
__device__ float g_xg[(size_t)BATCH * IN_DIM];        // gathered x (tf32-rounded)
__device__ float g_hg[(size_t)BATCH * HID_DIM];       // gathered hidden (tf32-rounded)

__device__ __forceinline__ float tf32r(float f) {
    float o;
    asm("cvt.rna.tf32.f32 %0, %1;" : "=f"(o) : "f"(f));
    return o;
}

// ---------------- small kernels ----------------
__global__ void zero_kernel() {
    int t = threadIdx.x;
    if (t < N_EXP) { g_counts[t] = 0; g_cursor[t] = 0; }
}

__global__ void router_kernel(const float* __restrict__ x,
                              const float* __restrict__ rw,
                              const float* __restrict__ rb,
                              float* __restrict__ route_out) {
    int warp = (blockIdx.x * blockDim.x + threadIdx.x) >> 5;
    int lane = threadIdx.x & 31;
    if (warp >= BATCH) return;
    const float* xr = x + (size_t)warp * IN_DIM;
    float acc[N_EXP];
#pragma unroll
    for (int e = 0; e < N_EXP; e++) acc[e] = 0.f;
    for (int k = lane; k < IN_DIM; k += 32) {
        float xv = xr[k];
        const float4* w4 = reinterpret_cast<const float4*>(rw + (size_t)k * N_EXP);
        float4 w0 = w4[0], w1 = w4[1];
        acc[0] += xv * w0.x; acc[1] += xv * w0.y;
        acc[2] += xv * w0.z; acc[3] += xv * w0.w;
        acc[4] += xv * w1.x; acc[5] += xv * w1.y;
        acc[6] += xv * w1.z; acc[7] += xv * w1.w;
    }
#pragma unroll
    for (int e = 0; e < N_EXP; e++) {
#pragma unroll
        for (int off = 16; off > 0; off >>= 1)
            acc[e] += __shfl_down_sync(0xffffffffu, acc[e], off);
    }
    if (lane == 0) {
        float best = acc[0] + rb[0]; int bi = 0;
#pragma unroll
        for (int e = 1; e < N_EXP; e++) {
            float v = acc[e] + rb[e];
            if (v > best) { best = v; bi = e; }   // first-max wins == jnp.argmax
        }
        g_expert_of[warp] = bi;
        atomicAdd(&g_counts[bi], 1);
        float* ro = route_out + (size_t)warp * N_EXP;
#pragma unroll
        for (int e = 0; e < N_EXP; e++) ro[e] = (e == bi) ? 1.f : 0.f;
    }
}

__global__ void scan_kernel() {
    if (threadIdx.x == 0) {
        int s = 0;
        for (int e = 0; e < N_EXP; e++) { g_offsets[e] = s; s += g_counts[e]; }
    }
}

__global__ void gather_kernel(const float* __restrict__ x) {
    int warp = (blockIdx.x * blockDim.x + threadIdx.x) >> 5;
    int lane = threadIdx.x & 31;
    if (warp >= BATCH) return;
    int e = g_expert_of[warp];
    int pos = 0;
    if (lane == 0) {
        pos = g_offsets[e] + atomicAdd(&g_cursor[e], 1);
        g_perm[pos] = warp;
    }
    pos = __shfl_sync(0xffffffffu, pos, 0);
    const float4* src = reinterpret_cast<const float4*>(x + (size_t)warp * IN_DIM);
    float4* dst = reinterpret_cast<float4*>(g_xg + (size_t)pos * IN_DIM);
    for (int i = lane; i < IN_DIM / 4; i += 32) {
        float4 v = src[i];
        v.x = tf32r(v.x); v.y = tf32r(v.y); v.z = tf32r(v.z); v.w = tf32r(v.w);
        dst[i] = v;
    }
}

// ---------------- tf32 mma.sync GEMM ----------------
constexpr int BM = 128, BN = 128, BK = 32, THREADS = 256;
constexpr int AST = BK + 4;   // 36 floats: conflict-free A frag reads
constexpr int BST = BN + 4;   // 132 floats: conflict-free B frag reads
constexpr int SMEM_BYTES = (2 * BM * AST + 2 * BK * BST) * 4;  // 70656 B

__device__ __forceinline__ void cp_async16(float* sm, const float* g, bool p) {
    uint32_t s = (uint32_t)__cvta_generic_to_shared(sm);
    int bytes = p ? 16 : 0;
    asm volatile("cp.async.cg.shared.global [%0], [%1], 16, %2;\n"
                 :: "r"(s), "l"(g), "r"(bytes));
}
__device__ __forceinline__ void cp_commit() { asm volatile("cp.async.commit_group;\n"); }
template <int N> __device__ __forceinline__ void cp_wait() {
    asm volatile("cp.async.wait_group %0;\n" :: "n"(N));
}

__device__ __forceinline__ void mma_tf32(float* c, const uint32_t* a, const uint32_t* b) {
    asm volatile(
        "mma.sync.aligned.m16n8k8.row.col.f32.tf32.tf32.f32 "
        "{%0,%1,%2,%3}, {%4,%5,%6,%7}, {%8,%9}, {%0,%1,%2,%3};\n"
        : "+f"(c[0]), "+f"(c[1]), "+f"(c[2]), "+f"(c[3])
        : "r"(a[0]), "r"(a[1]), "r"(a[2]), "r"(a[3]), "r"(b[0]), "r"(b[1]));
}

template <bool EXPERT>
__global__ __launch_bounds__(THREADS)
void gemm_tf32_kernel(const float* __restrict__ Bglob,
                      const float* __restrict__ biasGlob,
                      float* __restrict__ outGlob) {
    constexpr int Ksz = EXPERT ? IN_DIM : HID_DIM;
    constexpr int Nsz = EXPERT ? HID_DIM : OUT_DIM;
    constexpr int KT = Ksz / BK;

    int M;
    const float *A, *B, *bias;
    float* C;
    if constexpr (EXPERT) {
        int e = blockIdx.z;
        M    = g_counts[e];
        A    = g_xg + (size_t)g_offsets[e] * IN_DIM;
        B    = Bglob + (size_t)e * IN_DIM * HID_DIM;
        bias = biasGlob + (size_t)e * HID_DIM;
        C    = g_hg + (size_t)g_offsets[e] * HID_DIM;
    } else {
        M = BATCH; A = g_hg; B = Bglob; bias = biasGlob; C = outGlob;
    }
    int m_blk = blockIdx.y * BM;
    if (m_blk >= M) return;     // ragged per-expert M: cheap early-exit
    int n_blk = blockIdx.x * BN;

    extern __shared__ float smem[];
    float* As = smem;                    // [2][BM][AST], row-major (m,k)
    float* Bs = smem + 2 * BM * AST;     // [2][BK][BST], row-major (k,n)

    int tid = threadIdx.x;
    int a_row = tid >> 3;
    int a_col = (tid & 7) * 4;
    int b_row = tid >> 5;
    int b_col = (tid & 31) * 4;

    auto load_tiles = [&](int kt, int s) {
        float* Ad = As + s * BM * AST;
#pragma unroll
        for (int i = 0; i < 4; i++) {
            int r = a_row + i * 32;
            int gr = m_blk + r;
            bool ok = gr < M;
            const float* src = A + (size_t)(ok ? gr : 0) * Ksz + kt * BK + a_col;
            cp_async16(Ad + r * AST + a_col, src, ok);
        }
        float* Bd = Bs + s * BK * BST;
#pragma unroll
        for (int i = 0; i < 4; i++) {
            int r = b_row + i * 8;
            const float* src = B + (size_t)(kt * BK + r) * Nsz + n_blk + b_col;
            cp_async16(Bd + r * BST + b_col, src, true);
        }
        cp_commit();
    };

    float acc[4][4][4];
#pragma unroll
    for (int i = 0; i < 4; i++)
#pragma unroll
        for (int j = 0; j < 4; j++)
#pragma unroll
            for (int q = 0; q < 4; q++) acc[i][j][q] = 0.f;

    int lane = tid & 31, warp = tid >> 5;
    int wm = warp & 1, wn = warp >> 1;     // 2 warps along M, 4 along N
    int gq = lane >> 2, tg = lane & 3;

    load_tiles(0, 0);
    int cur = 0;
    for (int kt = 0; kt < KT; kt++) {
        if (kt + 1 < KT) { load_tiles(kt + 1, cur ^ 1); cp_wait<1>(); }
        else             { cp_wait<0>(); }
        __syncthreads();
        float* Ab = As + cur * BM * AST;
        float* Bb = Bs + cur * BK * BST;
#pragma unroll
        for (int ks = 0; ks < 4; ks++) {
            int k0 = ks * 8 + tg;
            uint32_t af[4][4], bf[4][2];
#pragma unroll
            for (int i = 0; i < 4; i++) {
                int r = wm * 64 + i * 16 + gq;
                af[i][0] = __float_as_uint(Ab[r * AST + k0]);
                af[i][1] = __float_as_uint(Ab[(r + 8) * AST + k0]);
                af[i][2] = __float_as_uint(Ab[r * AST + k0 + 4]);
                af[i][3] = __float_as_uint(Ab[(r + 8) * AST + k0 + 4]);
            }
#pragma unroll
            for (int j = 0; j < 4; j++) {
                int n = wn * 32 + j * 8 + gq;
                bf[j][0] = __float_as_uint(tf32r(Bb[k0 * BST + n]));
                bf[j][1] = __float_as_uint(tf32r(Bb[(k0 + 4) * BST + n]));
            }
#pragma unroll
            for (int i = 0; i < 4; i++)
#pragma unroll
                for (int j = 0; j < 4; j++)
                    mma_tf32(acc[i][j], af[i], bf[j]);
        }
        __syncthreads();
        cur ^= 1;
    }

    // epilogue
#pragma unroll
    for (int i = 0; i < 4; i++) {
        int r0 = m_blk + wm * 64 + i * 16 + gq;
        int r1 = r0 + 8;
#pragma unroll
        for (int j = 0; j < 4; j++) {
            int c = n_blk + wn * 32 + j * 8 + tg * 2;
            float bv0 = bias[c], bv1 = bias[c + 1];
            float v00 = acc[i][j][0] + bv0;
            float v01 = acc[i][j][1] + bv1;
            float v10 = acc[i][j][2] + bv0;
            float v11 = acc[i][j][3] + bv1;
            if constexpr (EXPERT) {
                if (r0 < M) {
                    C[(size_t)r0 * Nsz + c]     = tf32r(v00);
                    C[(size_t)r0 * Nsz + c + 1] = tf32r(v01);
                }
                if (r1 < M) {
                    C[(size_t)r1 * Nsz + c]     = tf32r(v10);
                    C[(size_t)r1 * Nsz + c + 1] = tf32r(v11);
                }
            } else {
                int o0 = g_perm[r0], o1 = g_perm[r1];   // scatter rows back
                C[(size_t)o0 * Nsz + c]     = v00;
                C[(size_t)o0 * Nsz + c + 1] = v01;
                C[(size_t)o1 * Nsz + c]     = v10;
                C[(size_t)o1 * Nsz + c + 1] = v11;
            }
        }
    }
}

// ---------------- launch ----------------
extern "C" void kernel_launch(void* const* d_in, const int* in_sizes, int n_in,
                              void* d_out, int out_size) {
    const float* x        = (const float*)d_in[0];
    const float* router_w = (const float*)d_in[1];
    const float* router_b = (const float*)d_in[2];
    const float* expert_w = (const float*)d_in[3];
    const float* expert_b = (const float*)d_in[4];
    const float* proj_w   = (const float*)d_in[5];
    const float* proj_b   = (const float*)d_in[6];

    float* out       = (float*)d_out;
    float* route_out = out + (size_t)BATCH * OUT_DIM;   // [out | one_hot]

    cudaFuncSetAttribute(gemm_tf32_kernel<true>,
                         cudaFuncAttributeMaxDynamicSharedMemorySize, SMEM_BYTES);
    cudaFuncSetAttribute(gemm_tf32_kernel<false>,
                         cudaFuncAttributeMaxDynamicSharedMemorySize, SMEM_BYTES);

    zero_kernel<<<1, 32>>>();
    router_kernel<<<BATCH / 8, 256>>>(x, router_w, router_b, route_out);
    scan_kernel<<<1, 1>>>();
    gather_kernel<<<BATCH / 8, 256>>>(x);
    gemm_tf32_kernel<true><<<dim3(HID_DIM / BN, BATCH / BM, N_EXP),
                             THREADS, SMEM_BYTES>>>(expert_w, expert_b, nullptr);
    gemm_tf32_kernel<false><<<dim3(OUT_DIM / BN, BATCH / BM, 1),
                              THREADS, SMEM_BYTES>>>(proj_w, proj_b, out);
}